// round 4
// baseline (speedup 1.0000x reference)
#include <cuda_runtime.h>

#define D   33
#define DD  (33 * 33)
#define NL  (33 * 33 * 33)   // 35937
#define NBASIS 8

// Combined (softmax-weighted) LUTs, layout [stage][b*DD + g*D + r] = {R,G,B,pad}
__device__ float4 g_clut[2][NL];

// ---------------------------------------------------------------------------
// Kernel 1: combine 8 basis LUTs with softmax weights, repack to float4.
// lut layout: [2][8][3][D][D][D], innermost index contiguous across threads.
// ---------------------------------------------------------------------------
__global__ void build_clut_kernel(const float* __restrict__ lut,
                                  const float* __restrict__ lc0,
                                  const float* __restrict__ lc1) {
    int i = blockIdx.x * blockDim.x + threadIdx.x;
    if (i >= NL) return;

    // per-thread softmax over 8 (cheap; lc hits constant-cached L1)
    float w[2][NBASIS];
    #pragma unroll
    for (int s = 0; s < 2; s++) {
        const float* lc = (s == 0) ? lc0 : lc1;
        float m = -1e30f;
        #pragma unroll
        for (int n = 0; n < NBASIS; n++) m = fmaxf(m, __ldg(lc + n));
        float sum = 0.f;
        #pragma unroll
        for (int n = 0; n < NBASIS; n++) { w[s][n] = __expf(__ldg(lc + n) - m); sum += w[s][n]; }
        float inv = 1.0f / sum;
        #pragma unroll
        for (int n = 0; n < NBASIS; n++) w[s][n] *= inv;
    }

    #pragma unroll
    for (int s = 0; s < 2; s++) {
        float acc[3] = {0.f, 0.f, 0.f};
        #pragma unroll
        for (int n = 0; n < NBASIS; n++) {
            const float* basep = lut + (((size_t)s * NBASIS + n) * 3) * NL + i;
            #pragma unroll
            for (int c = 0; c < 3; c++)
                acc[c] = fmaf(w[s][n], __ldg(basep + (size_t)c * NL), acc[c]);
        }
        g_clut[s][i] = make_float4(acc[0], acc[1], acc[2], 0.f);
    }
}

// ---------------------------------------------------------------------------
// Trilinear lookup: one float4 per corner carries all 3 channels.
// ---------------------------------------------------------------------------
__device__ __forceinline__ float3 lut3d(const float4* __restrict__ L,
                                        float r, float g, float b) {
    r = fminf(fmaxf(r, 0.f), 1.f) * (float)(D - 1);
    g = fminf(fmaxf(g, 0.f), 1.f) * (float)(D - 1);
    b = fminf(fmaxf(b, 0.f), 1.f) * (float)(D - 1);

    int ir = min((int)r, D - 2);
    int ig = min((int)g, D - 2);
    int ib = min((int)b, D - 2);
    float fr = r - (float)ir;
    float fg = g - (float)ig;
    float fb = b - (float)ib;

    int idx = ib * DD + ig * D + ir;

    float4 c000 = __ldg(L + idx);
    float4 c001 = __ldg(L + idx + 1);
    float4 c010 = __ldg(L + idx + D);
    float4 c011 = __ldg(L + idx + D + 1);
    float4 c100 = __ldg(L + idx + DD);
    float4 c101 = __ldg(L + idx + DD + 1);
    float4 c110 = __ldg(L + idx + DD + D);
    float4 c111 = __ldg(L + idx + DD + D + 1);

    // lerp along r
    float a00x = fmaf(fr, c001.x - c000.x, c000.x);
    float a00y = fmaf(fr, c001.y - c000.y, c000.y);
    float a00z = fmaf(fr, c001.z - c000.z, c000.z);
    float a01x = fmaf(fr, c011.x - c010.x, c010.x);
    float a01y = fmaf(fr, c011.y - c010.y, c010.y);
    float a01z = fmaf(fr, c011.z - c010.z, c010.z);
    float a10x = fmaf(fr, c101.x - c100.x, c100.x);
    float a10y = fmaf(fr, c101.y - c100.y, c100.y);
    float a10z = fmaf(fr, c101.z - c100.z, c100.z);
    float a11x = fmaf(fr, c111.x - c110.x, c110.x);
    float a11y = fmaf(fr, c111.y - c110.y, c110.y);
    float a11z = fmaf(fr, c111.z - c110.z, c110.z);
    // lerp along g
    float b0x = fmaf(fg, a01x - a00x, a00x);
    float b0y = fmaf(fg, a01y - a00y, a00y);
    float b0z = fmaf(fg, a01z - a00z, a00z);
    float b1x = fmaf(fg, a11x - a10x, a10x);
    float b1y = fmaf(fg, a11y - a10y, a10y);
    float b1z = fmaf(fg, a11z - a10z, a10z);
    // lerp along b
    float3 o;
    o.x = fmaf(fb, b1x - b0x, b0x);
    o.y = fmaf(fb, b1y - b0y, b0y);
    o.z = fmaf(fb, b1z - b0z, b0z);
    return o;
}

// ---------------------------------------------------------------------------
// Kernel 2: fused dual-LUT application. 4 pixels / thread via float4 I/O.
// gt / out layout: planar [3][H*W].
// ---------------------------------------------------------------------------
#define PIX_PER_THREAD 4

__global__ __launch_bounds__(256)
void apply_lut_kernel(const float* __restrict__ gt,
                      float* __restrict__ out, int hw) {
    int t = blockIdx.x * blockDim.x + threadIdx.x;
    int base = t * PIX_PER_THREAD;
    if (base >= hw) return;

    const float4 r4 = *reinterpret_cast<const float4*>(gt + base);
    const float4 g4 = *reinterpret_cast<const float4*>(gt + hw + base);
    const float4 b4 = *reinterpret_cast<const float4*>(gt + 2 * hw + base);

    float ri[4] = {r4.x, r4.y, r4.z, r4.w};
    float gi[4] = {g4.x, g4.y, g4.z, g4.w};
    float bi[4] = {b4.x, b4.y, b4.z, b4.w};
    float ro[4], go[4], bo[4];

    const float4* L0 = g_clut[0];
    const float4* L1 = g_clut[1];

    #pragma unroll
    for (int p = 0; p < PIX_PER_THREAD; p++) {
        float3 s = lut3d(L0, ri[p], gi[p], bi[p]);
        float3 f = lut3d(L1, s.x, s.y, s.z);
        ro[p] = f.x; go[p] = f.y; bo[p] = f.z;
    }

    *reinterpret_cast<float4*>(out + base)          = make_float4(ro[0], ro[1], ro[2], ro[3]);
    *reinterpret_cast<float4*>(out + hw + base)     = make_float4(go[0], go[1], go[2], go[3]);
    *reinterpret_cast<float4*>(out + 2 * hw + base) = make_float4(bo[0], bo[1], bo[2], bo[3]);
}

// ---------------------------------------------------------------------------
extern "C" void kernel_launch(void* const* d_in, const int* in_sizes, int n_in,
                              void* d_out, int out_size) {
    const float* gt  = (const float*)d_in[0];   // [3, 2160, 3840]
    const float* lut = (const float*)d_in[1];   // [2, 8, 3, 33, 33, 33]
    const float* lc0 = (const float*)d_in[2];   // [8]
    const float* lc1 = (const float*)d_in[3];   // [8]
    float* out = (float*)d_out;

    const int hw = in_sizes[0] / 3;             // 8294400

    {
        int threads = 128;
        int blocks  = (NL + threads - 1) / threads;
        build_clut_kernel<<<blocks, threads>>>(lut, lc0, lc1);
    }
    {
        int threads = 256;
        int total_threads = hw / PIX_PER_THREAD;
        int blocks = (total_threads + threads - 1) / threads;
        apply_lut_kernel<<<blocks, threads>>>(gt, out, hw);
    }
}

// round 6
// speedup vs baseline: 1.7728x; 1.7728x over previous
#include <cuda_runtime.h>

#define D   33
#define DD  (33 * 33)
#define NL  (33 * 33 * 33)   // 35937
#define NBASIS 8

#define QMAXF 2097151.0f     // 2^21 - 1
#define BIASF 8388608.0f     // 2^23
#define EXPB  0x4B000000u    // float bits of 2^23

// Intermediate combined LUTs (fp32) and final packed pair records.
// g_pack[s][b*DD+g*D+r] packs corners (r, r+1) x {R,G,B} as 6 x 21-bit
// fixed-point: .x = R0 | G0<<21 | B0<<42 ; .y = R1 | G1<<21 | B1<<42.
__device__ float4     g_clut[2][NL];
__device__ ulonglong2 g_pack[2][NL];

// ---------------------------------------------------------------------------
// Kernel 1: combine 8 basis LUTs with softmax weights (fp32).
// ---------------------------------------------------------------------------
__global__ void build_clut_kernel(const float* __restrict__ lut,
                                  const float* __restrict__ lc0,
                                  const float* __restrict__ lc1) {
    int i = blockIdx.x * blockDim.x + threadIdx.x;
    if (i >= NL) return;

    float w[2][NBASIS];
    #pragma unroll
    for (int s = 0; s < 2; s++) {
        const float* lc = (s == 0) ? lc0 : lc1;
        float m = -1e30f;
        #pragma unroll
        for (int n = 0; n < NBASIS; n++) m = fmaxf(m, __ldg(lc + n));
        float sum = 0.f;
        #pragma unroll
        for (int n = 0; n < NBASIS; n++) { w[s][n] = __expf(__ldg(lc + n) - m); sum += w[s][n]; }
        float inv = 1.0f / sum;
        #pragma unroll
        for (int n = 0; n < NBASIS; n++) w[s][n] *= inv;
    }

    #pragma unroll
    for (int s = 0; s < 2; s++) {
        float acc[3] = {0.f, 0.f, 0.f};
        #pragma unroll
        for (int n = 0; n < NBASIS; n++) {
            const float* basep = lut + (((size_t)s * NBASIS + n) * 3) * NL + i;
            #pragma unroll
            for (int c = 0; c < 3; c++)
                acc[c] = fmaf(w[s][n], __ldg(basep + (size_t)c * NL), acc[c]);
        }
        g_clut[s][i] = make_float4(acc[0], acc[1], acc[2], 0.f);
    }
}

// ---------------------------------------------------------------------------
// Kernel 2: pack r-pairs into 21-bit fixed-point 16B records.
// ---------------------------------------------------------------------------
__device__ __forceinline__ unsigned long long q21(float v) {
    v = fminf(fmaxf(v, 0.f), 1.f);
    return (unsigned long long)(v * QMAXF + 0.5f);
}

__global__ void pack_clut_kernel() {
    int i = blockIdx.x * blockDim.x + threadIdx.x;
    if (i >= 2 * NL) return;
    int s   = (i >= NL) ? 1 : 0;
    int idx = i - s * NL;
    int ir  = idx % D;

    unsigned long long u0 = 0, u1 = 0;
    if (ir < D - 1) {
        float4 c0 = g_clut[s][idx];
        float4 c1 = g_clut[s][idx + 1];
        u0 = q21(c0.x) | (q21(c0.y) << 21) | (q21(c0.z) << 42);
        u1 = q21(c1.x) | (q21(c1.y) << 21) | (q21(c1.z) << 42);
    }
    g_pack[s][idx] = make_ulonglong2(u0, u1);
}

// ---------------------------------------------------------------------------
// Decode: 21-bit field -> float (q + 2^23) via exponent-OR. Bias cancels in
// lerp differences; subtracted once per channel at the end.
// ---------------------------------------------------------------------------
__device__ __forceinline__ void dec3(unsigned long long u,
                                     float& x, float& y, float& z) {
    x = __uint_as_float(EXPB | (unsigned)(u & 0x1FFFFFull));
    y = __uint_as_float(EXPB | (unsigned)((u >> 21) & 0x1FFFFFull));
    z = __uint_as_float(EXPB | (unsigned)(u >> 42));
}

__device__ __forceinline__ float3 lut3d_q(const ulonglong2* __restrict__ L,
                                          float r, float g, float b) {
    r = fminf(fmaxf(r, 0.f), 1.f) * (float)(D - 1);
    g = fminf(fmaxf(g, 0.f), 1.f) * (float)(D - 1);
    b = fminf(fmaxf(b, 0.f), 1.f) * (float)(D - 1);

    int ir = min((int)r, D - 2);
    int ig = min((int)g, D - 2);
    int ib = min((int)b, D - 2);
    float fr = r - (float)ir;
    float fg = g - (float)ig;
    float fb = b - (float)ib;

    int idx = ib * DD + ig * D + ir;

    // 4 loads per pixel-stage (each record = both r-corners, all channels)
    ulonglong2 u00 = __ldg(L + idx);
    ulonglong2 u01 = __ldg(L + idx + D);
    ulonglong2 u10 = __ldg(L + idx + DD);
    ulonglong2 u11 = __ldg(L + idx + DD + D);

    float R0, G0, B0, R1, G1, B1;

    dec3(u00.x, R0, G0, B0); dec3(u00.y, R1, G1, B1);
    float a00x = fmaf(fr, R1 - R0, R0);
    float a00y = fmaf(fr, G1 - G0, G0);
    float a00z = fmaf(fr, B1 - B0, B0);

    dec3(u01.x, R0, G0, B0); dec3(u01.y, R1, G1, B1);
    float a01x = fmaf(fr, R1 - R0, R0);
    float a01y = fmaf(fr, G1 - G0, G0);
    float a01z = fmaf(fr, B1 - B0, B0);

    dec3(u10.x, R0, G0, B0); dec3(u10.y, R1, G1, B1);
    float a10x = fmaf(fr, R1 - R0, R0);
    float a10y = fmaf(fr, G1 - G0, G0);
    float a10z = fmaf(fr, B1 - B0, B0);

    dec3(u11.x, R0, G0, B0); dec3(u11.y, R1, G1, B1);
    float a11x = fmaf(fr, R1 - R0, R0);
    float a11y = fmaf(fr, G1 - G0, G0);
    float a11z = fmaf(fr, B1 - B0, B0);

    float b0x = fmaf(fg, a01x - a00x, a00x);
    float b0y = fmaf(fg, a01y - a00y, a00y);
    float b0z = fmaf(fg, a01z - a00z, a00z);
    float b1x = fmaf(fg, a11x - a10x, a10x);
    float b1y = fmaf(fg, a11y - a10y, a10y);
    float b1z = fmaf(fg, a11z - a10z, a10z);

    float tx = fmaf(fb, b1x - b0x, b0x);
    float ty = fmaf(fb, b1y - b0y, b0y);
    float tz = fmaf(fb, b1z - b0z, b0z);

    const float sc = 1.0f / QMAXF;
    return make_float3((tx - BIASF) * sc, (ty - BIASF) * sc, (tz - BIASF) * sc);
}

// ---------------------------------------------------------------------------
// Kernel 3: fused dual-LUT application. 4 pixels / thread via float4 I/O.
// ---------------------------------------------------------------------------
#define PIX_PER_THREAD 4

__global__ __launch_bounds__(256)
void apply_lut_kernel(const float* __restrict__ gt,
                      float* __restrict__ out, int hw) {
    int t = blockIdx.x * blockDim.x + threadIdx.x;
    int base = t * PIX_PER_THREAD;
    if (base >= hw) return;

    const float4 r4 = *reinterpret_cast<const float4*>(gt + base);
    const float4 g4 = *reinterpret_cast<const float4*>(gt + hw + base);
    const float4 b4 = *reinterpret_cast<const float4*>(gt + 2 * hw + base);

    float ri[4] = {r4.x, r4.y, r4.z, r4.w};
    float gi[4] = {g4.x, g4.y, g4.z, g4.w};
    float bi[4] = {b4.x, b4.y, b4.z, b4.w};
    float ro[4], go[4], bo[4];

    const ulonglong2* L0 = g_pack[0];
    const ulonglong2* L1 = g_pack[1];

    #pragma unroll
    for (int p = 0; p < PIX_PER_THREAD; p++) {
        float3 s = lut3d_q(L0, ri[p], gi[p], bi[p]);
        float3 f = lut3d_q(L1, s.x, s.y, s.z);
        ro[p] = f.x; go[p] = f.y; bo[p] = f.z;
    }

    *reinterpret_cast<float4*>(out + base)          = make_float4(ro[0], ro[1], ro[2], ro[3]);
    *reinterpret_cast<float4*>(out + hw + base)     = make_float4(go[0], go[1], go[2], go[3]);
    *reinterpret_cast<float4*>(out + 2 * hw + base) = make_float4(bo[0], bo[1], bo[2], bo[3]);
}

// ---------------------------------------------------------------------------
extern "C" void kernel_launch(void* const* d_in, const int* in_sizes, int n_in,
                              void* d_out, int out_size) {
    const float* gt  = (const float*)d_in[0];   // [3, 2160, 3840]
    const float* lut = (const float*)d_in[1];   // [2, 8, 3, 33, 33, 33]
    const float* lc0 = (const float*)d_in[2];   // [8]
    const float* lc1 = (const float*)d_in[3];   // [8]
    float* out = (float*)d_out;

    const int hw = in_sizes[0] / 3;             // 8294400

    {
        int threads = 128;
        int blocks  = (NL + threads - 1) / threads;
        build_clut_kernel<<<blocks, threads>>>(lut, lc0, lc1);
    }
    {
        int threads = 256;
        int blocks  = (2 * NL + threads - 1) / threads;
        pack_clut_kernel<<<blocks, threads>>>();
    }
    {
        int threads = 256;
        int total_threads = hw / PIX_PER_THREAD;
        int blocks = (total_threads + threads - 1) / threads;
        apply_lut_kernel<<<blocks, threads>>>(gt, out, hw);
    }
}

// round 7
// speedup vs baseline: 2.0429x; 1.1523x over previous
#include <cuda_runtime.h>

#define D   33
#define DD  (33 * 33)
#define NL  (33 * 33 * 33)   // 35937
#define NBASIS 8

#define QMAXF  2097151.0f    // 2^21 - 1  (stage-1 pair records)
#define Q11F   2047.0f       // 2^11 - 1  (stage-2 R,G)
#define Q10F   1023.0f       // 2^10 - 1  (stage-2 B)
#define BIASF  8388608.0f    // 2^23
#define EXPB   0x4B000000u   // float bits of 2^23

// Combined LUTs (fp32 intermediate), then two packed formats:
//  g_pack1[idx]: stage-1, r-pair, 6 x 21-bit  (.x = R0|G0<<21|B0<<42, .y = r+1)
//  g_pack2[idx]: stage-2, (r,g)-quad, 4 words of R:11|G:11<<11|B:10<<22
__device__ float4     g_clut[2][NL];
__device__ ulonglong2 g_pack1[NL];
__device__ uint4      g_pack2[NL];

// ---------------------------------------------------------------------------
// Kernel 1: combine 8 basis LUTs with softmax weights (fp32).
// One thread per (stage, entry) -> 2*NL threads for latency hiding.
// ---------------------------------------------------------------------------
__global__ void build_clut_kernel(const float* __restrict__ lut,
                                  const float* __restrict__ lc0,
                                  const float* __restrict__ lc1) {
    int t = blockIdx.x * blockDim.x + threadIdx.x;
    if (t >= 2 * NL) return;
    int s = (t >= NL) ? 1 : 0;
    int i = t - s * NL;

    const float* lc = (s == 0) ? lc0 : lc1;
    float w[NBASIS];
    float m = -1e30f;
    #pragma unroll
    for (int n = 0; n < NBASIS; n++) m = fmaxf(m, __ldg(lc + n));
    float sum = 0.f;
    #pragma unroll
    for (int n = 0; n < NBASIS; n++) { w[n] = __expf(__ldg(lc + n) - m); sum += w[n]; }
    float inv = 1.0f / sum;

    float acc[3] = {0.f, 0.f, 0.f};
    #pragma unroll
    for (int n = 0; n < NBASIS; n++) {
        const float* basep = lut + (((size_t)s * NBASIS + n) * 3) * NL + i;
        float wn = w[n] * inv;
        #pragma unroll
        for (int c = 0; c < 3; c++)
            acc[c] = fmaf(wn, __ldg(basep + (size_t)c * NL), acc[c]);
    }
    g_clut[s][i] = make_float4(acc[0], acc[1], acc[2], 0.f);
}

// ---------------------------------------------------------------------------
// Kernel 2: pack both formats.
// ---------------------------------------------------------------------------
__device__ __forceinline__ unsigned long long q21(float v) {
    v = fminf(fmaxf(v, 0.f), 1.f);
    return (unsigned long long)(v * QMAXF + 0.5f);
}
__device__ __forceinline__ unsigned qw(float4 c) {
    float r = fminf(fmaxf(c.x, 0.f), 1.f);
    float g = fminf(fmaxf(c.y, 0.f), 1.f);
    float b = fminf(fmaxf(c.z, 0.f), 1.f);
    unsigned R = (unsigned)(r * Q11F + 0.5f);
    unsigned G = (unsigned)(g * Q11F + 0.5f);
    unsigned B = (unsigned)(b * Q10F + 0.5f);
    return R | (G << 11) | (B << 22);
}

__global__ void pack_clut_kernel() {
    int idx = blockIdx.x * blockDim.x + threadIdx.x;
    if (idx >= NL) return;
    int rem = idx % DD;
    int ig  = rem / D;
    int ir  = rem % D;

    // stage-1: 21-bit r-pair
    unsigned long long u0 = 0, u1 = 0;
    if (ir < D - 1) {
        float4 c0 = g_clut[0][idx];
        float4 c1 = g_clut[0][idx + 1];
        u0 = q21(c0.x) | (q21(c0.y) << 21) | (q21(c0.z) << 42);
        u1 = q21(c1.x) | (q21(c1.y) << 21) | (q21(c1.z) << 42);
    }
    g_pack1[idx] = make_ulonglong2(u0, u1);

    // stage-2: 11/11/10-bit (r,g)-quad
    uint4 q = make_uint4(0, 0, 0, 0);
    if (ir < D - 1 && ig < D - 1) {
        q.x = qw(g_clut[1][idx]);          // (g  , r  )
        q.y = qw(g_clut[1][idx + 1]);      // (g  , r+1)
        q.z = qw(g_clut[1][idx + D]);      // (g+1, r  )
        q.w = qw(g_clut[1][idx + D + 1]);  // (g+1, r+1)
    }
    g_pack2[idx] = q;
}

// ---------------------------------------------------------------------------
// Decoders: exponent-OR -> biased floats (q + 2^23); bias cancels in lerp
// differences and is removed once per channel at the end.
// ---------------------------------------------------------------------------
__device__ __forceinline__ void dec3(unsigned long long u,
                                     float& x, float& y, float& z) {
    x = __uint_as_float(EXPB | (unsigned)(u & 0x1FFFFFull));
    y = __uint_as_float(EXPB | (unsigned)((u >> 21) & 0x1FFFFFull));
    z = __uint_as_float(EXPB | (unsigned)(u >> 42));
}
__device__ __forceinline__ void decq(unsigned w,
                                     float& R, float& G, float& B) {
    R = __uint_as_float(EXPB | (w & 0x7FFu));
    G = __uint_as_float(EXPB | ((w >> 11) & 0x7FFu));
    B = __uint_as_float(EXPB | (w >> 22));
}

__device__ __forceinline__ void coords(float r, float g, float b,
                                       int& idx, float& fr, float& fg, float& fb) {
    r = fminf(fmaxf(r, 0.f), 1.f) * (float)(D - 1);
    g = fminf(fmaxf(g, 0.f), 1.f) * (float)(D - 1);
    b = fminf(fmaxf(b, 0.f), 1.f) * (float)(D - 1);
    int ir = min((int)r, D - 2);
    int ig = min((int)g, D - 2);
    int ib = min((int)b, D - 2);
    fr = r - (float)ir;
    fg = g - (float)ig;
    fb = b - (float)ib;
    idx = ib * DD + ig * D + ir;
}

// Stage 1: 21-bit pair records, 4 loads.
__device__ __forceinline__ float3 lut3d_s1(float r, float g, float b) {
    int idx; float fr, fg, fb;
    coords(r, g, b, idx, fr, fg, fb);

    ulonglong2 u00 = __ldg(g_pack1 + idx);
    ulonglong2 u01 = __ldg(g_pack1 + idx + D);
    ulonglong2 u10 = __ldg(g_pack1 + idx + DD);
    ulonglong2 u11 = __ldg(g_pack1 + idx + DD + D);

    float R0, G0, B0, R1, G1, B1;

    dec3(u00.x, R0, G0, B0); dec3(u00.y, R1, G1, B1);
    float a00x = fmaf(fr, R1 - R0, R0);
    float a00y = fmaf(fr, G1 - G0, G0);
    float a00z = fmaf(fr, B1 - B0, B0);
    dec3(u01.x, R0, G0, B0); dec3(u01.y, R1, G1, B1);
    float a01x = fmaf(fr, R1 - R0, R0);
    float a01y = fmaf(fr, G1 - G0, G0);
    float a01z = fmaf(fr, B1 - B0, B0);
    dec3(u10.x, R0, G0, B0); dec3(u10.y, R1, G1, B1);
    float a10x = fmaf(fr, R1 - R0, R0);
    float a10y = fmaf(fr, G1 - G0, G0);
    float a10z = fmaf(fr, B1 - B0, B0);
    dec3(u11.x, R0, G0, B0); dec3(u11.y, R1, G1, B1);
    float a11x = fmaf(fr, R1 - R0, R0);
    float a11y = fmaf(fr, G1 - G0, G0);
    float a11z = fmaf(fr, B1 - B0, B0);

    float b0x = fmaf(fg, a01x - a00x, a00x);
    float b0y = fmaf(fg, a01y - a00y, a00y);
    float b0z = fmaf(fg, a01z - a00z, a00z);
    float b1x = fmaf(fg, a11x - a10x, a10x);
    float b1y = fmaf(fg, a11y - a10y, a10y);
    float b1z = fmaf(fg, a11z - a10z, a10z);

    float tx = fmaf(fb, b1x - b0x, b0x);
    float ty = fmaf(fb, b1y - b0y, b0y);
    float tz = fmaf(fb, b1z - b0z, b0z);

    const float sc = 1.0f / QMAXF;
    return make_float3((tx - BIASF) * sc, (ty - BIASF) * sc, (tz - BIASF) * sc);
}

// Stage 2: quad records, 2 loads.
__device__ __forceinline__ float3 lut3d_s2(float r, float g, float b) {
    int idx; float fr, fg, fb;
    coords(r, g, b, idx, fr, fg, fb);

    uint4 p0 = __ldg(g_pack2 + idx);        // plane b
    uint4 p1 = __ldg(g_pack2 + idx + DD);   // plane b+1

    float R00, G00, B00, R01, G01, B01, R10, G10, B10, R11, G11, B11;

    // plane 0
    decq(p0.x, R00, G00, B00); decq(p0.y, R01, G01, B01);
    decq(p0.z, R10, G10, B10); decq(p0.w, R11, G11, B11);
    float r0x = fmaf(fr, R01 - R00, R00);
    float r0y = fmaf(fr, G01 - G00, G00);
    float r0z = fmaf(fr, B01 - B00, B00);
    float r1x = fmaf(fr, R11 - R10, R10);
    float r1y = fmaf(fr, G11 - G10, G10);
    float r1z = fmaf(fr, B11 - B10, B10);
    float p0x = fmaf(fg, r1x - r0x, r0x);
    float p0y = fmaf(fg, r1y - r0y, r0y);
    float p0z = fmaf(fg, r1z - r0z, r0z);

    // plane 1
    decq(p1.x, R00, G00, B00); decq(p1.y, R01, G01, B01);
    decq(p1.z, R10, G10, B10); decq(p1.w, R11, G11, B11);
    r0x = fmaf(fr, R01 - R00, R00);
    r0y = fmaf(fr, G01 - G00, G00);
    r0z = fmaf(fr, B01 - B00, B00);
    r1x = fmaf(fr, R11 - R10, R10);
    r1y = fmaf(fr, G11 - G10, G10);
    r1z = fmaf(fr, B11 - B10, B10);
    float p1x = fmaf(fg, r1x - r0x, r0x);
    float p1y = fmaf(fg, r1y - r0y, r0y);
    float p1z = fmaf(fg, r1z - r0z, r0z);

    float tx = fmaf(fb, p1x - p0x, p0x);
    float ty = fmaf(fb, p1y - p0y, p0y);
    float tz = fmaf(fb, p1z - p0z, p0z);

    return make_float3((tx - BIASF) * (1.0f / Q11F),
                       (ty - BIASF) * (1.0f / Q11F),
                       (tz - BIASF) * (1.0f / Q10F));
}

// ---------------------------------------------------------------------------
// Kernel 3: fused dual-LUT application. 4 pixels / thread via float4 I/O.
// ---------------------------------------------------------------------------
#define PIX_PER_THREAD 4

__global__ __launch_bounds__(256)
void apply_lut_kernel(const float* __restrict__ gt,
                      float* __restrict__ out, int hw) {
    int t = blockIdx.x * blockDim.x + threadIdx.x;
    int base = t * PIX_PER_THREAD;
    if (base >= hw) return;

    const float4 r4 = *reinterpret_cast<const float4*>(gt + base);
    const float4 g4 = *reinterpret_cast<const float4*>(gt + hw + base);
    const float4 b4 = *reinterpret_cast<const float4*>(gt + 2 * hw + base);

    float ri[4] = {r4.x, r4.y, r4.z, r4.w};
    float gi[4] = {g4.x, g4.y, g4.z, g4.w};
    float bi[4] = {b4.x, b4.y, b4.z, b4.w};
    float ro[4], go[4], bo[4];

    #pragma unroll
    for (int p = 0; p < PIX_PER_THREAD; p++) {
        float3 s = lut3d_s1(ri[p], gi[p], bi[p]);
        float3 f = lut3d_s2(s.x, s.y, s.z);
        ro[p] = f.x; go[p] = f.y; bo[p] = f.z;
    }

    *reinterpret_cast<float4*>(out + base)          = make_float4(ro[0], ro[1], ro[2], ro[3]);
    *reinterpret_cast<float4*>(out + hw + base)     = make_float4(go[0], go[1], go[2], go[3]);
    *reinterpret_cast<float4*>(out + 2 * hw + base) = make_float4(bo[0], bo[1], bo[2], bo[3]);
}

// ---------------------------------------------------------------------------
extern "C" void kernel_launch(void* const* d_in, const int* in_sizes, int n_in,
                              void* d_out, int out_size) {
    const float* gt  = (const float*)d_in[0];   // [3, 2160, 3840]
    const float* lut = (const float*)d_in[1];   // [2, 8, 3, 33, 33, 33]
    const float* lc0 = (const float*)d_in[2];   // [8]
    const float* lc1 = (const float*)d_in[3];   // [8]
    float* out = (float*)d_out;

    const int hw = in_sizes[0] / 3;             // 8294400

    {
        int threads = 128;
        int blocks  = (2 * NL + threads - 1) / threads;
        build_clut_kernel<<<blocks, threads>>>(lut, lc0, lc1);
    }
    {
        int threads = 256;
        int blocks  = (NL + threads - 1) / threads;
        pack_clut_kernel<<<blocks, threads>>>();
    }
    {
        int threads = 256;
        int total_threads = hw / PIX_PER_THREAD;
        int blocks = (total_threads + threads - 1) / threads;
        apply_lut_kernel<<<blocks, threads>>>(gt, out, hw);
    }
}